// round 1
// baseline (speedup 1.0000x reference)
#include <cuda_runtime.h>
#include <math_constants.h>

// GraphPoolMol: masked neighborhood max-pool over graph Laplacian sparsity.
// B=64, MAX_ATOM=128, N_FEAT=128.
// out[b,i,f] = max_{j: L[b,i,j]!=0, j<n, i<n} x[b,j,f]   (diag of L is 1 => self included)
//              fallback x[b,i,f] if row has no neighbors; 0 if i>=n.

#define AT 128
#define NF 128
#define ROWS_CONC 4              // rows processed concurrently per block
#define ROW_GROUPS 4             // blocks per batch
#define ROWS_PER_BLOCK (AT / ROW_GROUPS)   // 32
#define THREADS (ROWS_CONC * NF) // 512

__global__ __launch_bounds__(THREADS, 2)
void graph_pool_mol_kernel(const float* __restrict__ xg,
                           const float* __restrict__ Lg,
                           const int* __restrict__ mol_slice,
                           float* __restrict__ outg)
{
    const int b  = blockIdx.x / ROW_GROUPS;
    const int rg = blockIdx.x % ROW_GROUPS;

    extern __shared__ float xs[];            // AT*NF floats = 64 KB
    __shared__ unsigned maskw[2][ROWS_CONC][4]; // double-buffered 128-bit masks

    const int n = mol_slice[2 * b];          // mol_slice[b, 0] = n_atoms

    // Stage x[b] into shared memory (coalesced float4 copy: 64 KB)
    {
        const float4* src = reinterpret_cast<const float4*>(xg + (size_t)b * AT * NF);
        float4* dst = reinterpret_cast<float4*>(xs);
        #pragma unroll
        for (int idx = threadIdx.x; idx < AT * NF / 4; idx += THREADS)
            dst[idx] = src[idx];
    }
    __syncthreads();

    const int f    = threadIdx.x & (NF - 1);   // feature / j index, 0..127
    const int ry   = threadIdx.x >> 7;         // concurrent-row slot, 0..3
    const int wrow = f >> 5;                   // warp within row, 0..3
    const int lane = f & 31;

    const float* Lb   = Lg + (size_t)b * AT * AT;
    float*       outb = outg + (size_t)b * AT * NF;

    #pragma unroll
    for (int it = 0; it < ROWS_PER_BLOCK / ROWS_CONC; ++it) {
        const int i = rg * ROWS_PER_BLOCK + it * ROWS_CONC + ry;
        const int buf = it & 1;

        // Build the 128-bit nonzero mask for row i (coalesced L read + ballot)
        {
            const float Lv = Lb[(size_t)i * AT + f];
            const bool nb = (Lv != 0.0f) && (f < n) && (i < n);
            const unsigned bal = __ballot_sync(0xffffffffu, nb);
            if (lane == 0) maskw[buf][ry][wrow] = bal;
        }
        __syncthreads();

        // Iterate set bits: gather-max from shared x
        float acc = -CUDART_INF_F;
        bool any = false;
        #pragma unroll
        for (int w = 0; w < 4; ++w) {
            unsigned m = maskw[buf][ry][w];
            any |= (m != 0u);
            while (m) {
                const int jj = (w << 5) + (__ffs(m) - 1);
                m &= (m - 1);
                acc = fmaxf(acc, xs[jj * NF + f]);
            }
        }

        const float xi = xs[i * NF + f];
        float res;
        if (i < n)
            res = any ? acc : xi;
        else
            res = 0.0f;
        outb[(size_t)i * NF + f] = res;
        // No trailing barrier needed: mask buffer is double-buffered (it&1),
        // so the next iteration writes the other buffer. The ballot/write of
        // iteration it+2 reusing this buffer is ordered by the __syncthreads
        // of iteration it+1.
    }
}

extern "C" void kernel_launch(void* const* d_in, const int* in_sizes, int n_in,
                              void* d_out, int out_size)
{
    const float* node_features = (const float*)d_in[0];
    const float* laplacian     = (const float*)d_in[1];
    const int*   mol_slice     = (const int*)d_in[2];
    // d_in[3] = l_slice (unused; redundant with mol_slice n_atoms)

    float* out = (float*)d_out;

    const int smem = AT * NF * sizeof(float); // 64 KB dynamic
    static bool attr_set = false;
    // cudaFuncSetAttribute is a host-side, non-stream call: safe under graph
    // capture and idempotent. Call unconditionally to avoid stateful guards.
    cudaFuncSetAttribute(graph_pool_mol_kernel,
                         cudaFuncAttributeMaxDynamicSharedMemorySize, smem);
    (void)attr_set;

    const int B = 64;
    graph_pool_mol_kernel<<<B * ROW_GROUPS, THREADS, smem>>>(
        node_features, laplacian, mol_slice, out);
}

// round 2
// speedup vs baseline: 1.1843x; 1.1843x over previous
#include <cuda_runtime.h>
#include <math_constants.h>

// GraphPoolMol: masked neighborhood max-pool over graph Laplacian sparsity.
// B=64, MAX_ATOM=128, N_FEAT=128.
// out[b,i,f] = max_{j: L[b,i,j]!=0, j<n, i<n} x[b,j,f]; 0 if i>=n.
// Diagonal of L is exactly 1 => for i<n the set always contains j=i, so the
// reference's "no neighbor" fallback never triggers for valid rows, and
// cnt==0 <=> i>=n.

#define AT 128
#define NF 128
#define ROW_GROUPS 4
#define RPB 32                 // rows per block
#define THREADS 512

__device__ __forceinline__ float4 fmax4(float4 a, float4 b) {
    return make_float4(fmaxf(a.x, b.x), fmaxf(a.y, b.y),
                       fmaxf(a.z, b.z), fmaxf(a.w, b.w));
}

__global__ __launch_bounds__(THREADS, 2)
void graph_pool_mol_kernel(const float* __restrict__ xg,
                           const float* __restrict__ Lg,
                           const int* __restrict__ mol_slice,
                           float* __restrict__ outg)
{
    const int b  = blockIdx.x >> 2;
    const int rg = blockIdx.x & 3;

    extern __shared__ float xs[];                 // AT*NF floats = 64 KB
    __shared__ unsigned      words[RPB][4];       // per-row 128-bit nonzero masks
    __shared__ unsigned char list[RPB][AT];       // compacted neighbor indices
    __shared__ int           cnts[RPB];

    const int n   = mol_slice[2 * b];             // mol_slice[b,0] = n_atoms
    const int tid = threadIdx.x;

    // ---- Stage x[b] into shared (coalesced float4, 64 KB) -----------------
    {
        const float4* src = reinterpret_cast<const float4*>(xg + (size_t)b * AT * NF);
        float4*       dst = reinterpret_cast<float4*>(xs);
        #pragma unroll
        for (int idx = tid; idx < AT * NF / 4; idx += THREADS)
            dst[idx] = src[idx];
    }

    // ---- Phase A: build compacted neighbor lists for all 32 rows ----------
    const int f    = tid & (AT - 1);   // j index within row, 0..127
    const int ry   = tid >> 7;         // which of 4 concurrent rows, 0..3
    const int wrow = f >> 5;           // ballot word index, 0..3
    const int lane = f & 31;
    const int base = rg * RPB;

    const float* Lb = Lg + (size_t)b * AT * AT;

    #pragma unroll
    for (int it = 0; it < RPB / 4; ++it) {
        const int r = it * 4 + ry;                // local row 0..31
        const int i = base + r;

        const float    Lv  = Lb[(size_t)i * AT + f];
        const bool     nb  = (Lv != 0.0f) && (f < n) && (i < n);
        const unsigned bal = __ballot_sync(0xffffffffu, nb);
        if (lane == 0) words[r][wrow] = bal;
        __syncthreads();                          // words visible to all 4 warps of row

        const unsigned w0 = words[r][0], w1 = words[r][1];
        const unsigned w2 = words[r][2], w3 = words[r][3];
        const int c0 = __popc(w0), c1 = __popc(w1), c2 = __popc(w2);
        const int cnt = c0 + c1 + c2 + __popc(w3);
        if (f == 0) cnts[r] = cnt;

        if (nb) {
            const unsigned myw = (wrow == 0) ? w0 : (wrow == 1) ? w1
                               : (wrow == 2) ? w2 : w3;
            const int pre = (wrow > 0 ? c0 : 0) + (wrow > 1 ? c1 : 0)
                          + (wrow > 2 ? c2 : 0);
            const int pos = pre + __popc(myw & ((1u << lane) - 1u));
            list[r][pos] = (unsigned char)f;
        }
        // Pad to a multiple of 4 with the self index (always in the max set
        // when cnt>0, since diag(L)=1 and cnt>0 implies i<n).
        const int cntpad = (cnt + 3) & ~3;
        if (f >= cnt && f < cntpad)
            list[r][f] = (unsigned char)i;
    }
    __syncthreads();

    // ---- Phase B: barrier-free vectorized gather ---------------------------
    // 16 rows concurrent: 32 threads per row, each thread owns 4 features.
    const int rb = tid >> 5;          // row slot, 0..15
    const int fl = tid & 31;          // float4 feature index, 0..31
    const float4* xs4  = reinterpret_cast<const float4*>(xs);
    float4*       out4 = reinterpret_cast<float4*>(outg + (size_t)b * AT * NF);

    #pragma unroll
    for (int it = 0; it < RPB / 16; ++it) {
        const int r   = it * 16 + rb;
        const int i   = base + r;
        const int cnt = cnts[r];

        float4 res;
        if (cnt == 0) {                           // i >= n
            res = make_float4(0.f, 0.f, 0.f, 0.f);
        } else {
            float4 a0 = make_float4(-CUDART_INF_F, -CUDART_INF_F,
                                    -CUDART_INF_F, -CUDART_INF_F);
            float4 a1 = a0, a2 = a0, a3 = a0;
            const unsigned char* lp = list[r];
            const int cp = (cnt + 3) & ~3;
            for (int k = 0; k < cp; k += 4) {
                // One broadcast LDS.32 fetches 4 neighbor indices.
                const uchar4 jj = *reinterpret_cast<const uchar4*>(lp + k);
                const float4 v0 = xs4[(int)jj.x * (NF / 4) + fl];
                const float4 v1 = xs4[(int)jj.y * (NF / 4) + fl];
                const float4 v2 = xs4[(int)jj.z * (NF / 4) + fl];
                const float4 v3 = xs4[(int)jj.w * (NF / 4) + fl];
                a0 = fmax4(a0, v0);
                a1 = fmax4(a1, v1);
                a2 = fmax4(a2, v2);
                a3 = fmax4(a3, v3);
            }
            res = fmax4(fmax4(a0, a1), fmax4(a2, a3));
        }
        out4[(size_t)i * (NF / 4) + fl] = res;
    }
}

extern "C" void kernel_launch(void* const* d_in, const int* in_sizes, int n_in,
                              void* d_out, int out_size)
{
    const float* node_features = (const float*)d_in[0];
    const float* laplacian     = (const float*)d_in[1];
    const int*   mol_slice     = (const int*)d_in[2];
    // d_in[3] = l_slice (unused)

    float* out = (float*)d_out;

    const int smem = AT * NF * sizeof(float);     // 64 KB dynamic
    cudaFuncSetAttribute(graph_pool_mol_kernel,
                         cudaFuncAttributeMaxDynamicSharedMemorySize, smem);

    const int B = 64;
    graph_pool_mol_kernel<<<B * ROW_GROUPS, THREADS, smem>>>(
        node_features, laplacian, mol_slice, out);
}

// round 3
// speedup vs baseline: 1.4345x; 1.2113x over previous
#include <cuda_runtime.h>
#include <math_constants.h>

// GraphPoolMol: masked neighborhood max-pool over graph Laplacian sparsity.
// B=64, MAX_ATOM=128, N_FEAT=128.
// out[b,i,f] = max_{j: L[b,i,j]!=0, j<n, i<n} x[b,j,f]; 0 if i>=n.
// diag(L)=1 => every valid row contains self => cnt==0 <=> i>=n, and padding
// the neighbor list with the self index never changes the max.

#define AT 128
#define NF 128
#define ROW_GROUPS 4
#define RPB 32                 // rows per block
#define THREADS 512
#define ITS 8                  // RPB*AT / THREADS  (phase-A items per thread)

__device__ __forceinline__ float4 fmax4(float4 a, float4 b) {
    return make_float4(fmaxf(a.x, b.x), fmaxf(a.y, b.y),
                       fmaxf(a.z, b.z), fmaxf(a.w, b.w));
}

__device__ __forceinline__ void cp_async16(void* smem_dst, const void* gsrc) {
    unsigned s = (unsigned)__cvta_generic_to_shared(smem_dst);
    asm volatile("cp.async.cg.shared.global [%0], [%1], 16;\n"
                 :: "r"(s), "l"(gsrc) : "memory");
}

__global__ __launch_bounds__(THREADS, 2)
void graph_pool_mol_kernel(const float* __restrict__ xg,
                           const float* __restrict__ Lg,
                           const int* __restrict__ mol_slice,
                           float* __restrict__ outg)
{
    const int b  = blockIdx.x >> 2;
    const int rg = blockIdx.x & 3;

    extern __shared__ float xs[];                 // AT*NF floats = 64 KB
    __shared__ unsigned      words[RPB][4];       // 128-bit nonzero masks
    __shared__ unsigned char list[RPB][AT];       // compacted neighbor indices
    __shared__ int           cnts[RPB];

    const int n   = mol_slice[2 * b];             // mol_slice[b,0] = n_atoms
    const int tid = threadIdx.x;

    // ---- Stage x[b] -> shared via cp.async (no regs, overlapped) ----------
    {
        const char* src = (const char*)(xg + (size_t)b * AT * NF);
        #pragma unroll
        for (int k = 0; k < 8; ++k) {
            const int byte = (tid + k * THREADS) * 16;   // 512*16*8 = 64KB
            cp_async16((char*)xs + byte, src + byte);
        }
        asm volatile("cp.async.commit_group;\n" ::: "memory");
    }

    const int f    = tid & (AT - 1);   // j index within row, 0..127
    const int ry   = tid >> 7;         // row slot, 0..3
    const int wrow = f >> 5;           // ballot word index, 0..3
    const int lane = f & 31;
    const int base = rg * RPB;

    const float* Lb = Lg + (size_t)b * AT * AT;

    // ---- Preload all L values (MLP=8, single memory epoch) ---------------
    float Lv[ITS];
    #pragma unroll
    for (int it = 0; it < ITS; ++it) {
        const int i = base + it * 4 + ry;
        Lv[it] = Lb[(size_t)i * AT + f];
    }

    // ---- All ballots, no barriers -----------------------------------------
    unsigned nbmask = 0;
    #pragma unroll
    for (int it = 0; it < ITS; ++it) {
        const int r = it * 4 + ry;
        const int i = base + r;
        const bool nb = (Lv[it] != 0.0f) && (f < n) && (i < n);
        nbmask |= nb ? (1u << it) : 0u;
        const unsigned bal = __ballot_sync(0xffffffffu, nb);
        if (lane == 0) words[r][wrow] = bal;
    }

    asm volatile("cp.async.wait_group 0;\n" ::: "memory");
    __syncthreads();   // words + staged xs visible to all

    // ---- Build compacted neighbor lists (pure LDS, no barriers) -----------
    #pragma unroll
    for (int it = 0; it < ITS; ++it) {
        const int r = it * 4 + ry;
        const int i = base + r;
        const uint4 w = *reinterpret_cast<const uint4*>(words[r]);
        const int c0 = __popc(w.x), c1 = __popc(w.y), c2 = __popc(w.z);
        const int cnt = c0 + c1 + c2 + __popc(w.w);
        if (f == 0) cnts[r] = cnt;

        if (nbmask & (1u << it)) {
            const unsigned myw = (wrow == 0) ? w.x : (wrow == 1) ? w.y
                               : (wrow == 2) ? w.z : w.w;
            const int pre = (wrow > 0 ? c0 : 0) + (wrow > 1 ? c1 : 0)
                          + (wrow > 2 ? c2 : 0);
            const int pos = pre + __popc(myw & ((1u << lane) - 1u));
            list[r][pos] = (unsigned char)f;
        }
        // Pad to a multiple of 8 with the self index.
        const int cntpad = (cnt + 7) & ~7;
        if (f >= cnt && f < cntpad)
            list[r][f] = (unsigned char)i;
    }
    __syncthreads();

    // ---- Gather: 32 rows in one pass, 16 threads/row, 8-neighbor unroll ---
    const int rb = tid >> 4;          // local row, 0..31
    const int fl = tid & 15;          // float4 slot, 0..15 (owns fl and fl+16)
    const int i  = base + rb;
    const int cnt = cnts[rb];
    const float4* xs4  = reinterpret_cast<const float4*>(xs);
    float4*       out4 = reinterpret_cast<float4*>(outg + (size_t)b * AT * NF);

    float4 resA, resB;
    if (cnt == 0) {                               // i >= n
        resA = make_float4(0.f, 0.f, 0.f, 0.f);
        resB = resA;
    } else {
        const float4 ninf = make_float4(-CUDART_INF_F, -CUDART_INF_F,
                                        -CUDART_INF_F, -CUDART_INF_F);
        float4 a0 = ninf, a1 = ninf, b0 = ninf, b1 = ninf;
        const unsigned char* lp = list[rb];
        const int cp = (cnt + 7) & ~7;
        for (int k = 0; k < cp; k += 8) {
            const uint2 w = *reinterpret_cast<const uint2*>(lp + k);  // 8 idx
            const int j0 =  w.x        & 0xff, j1 = (w.x >>  8) & 0xff;
            const int j2 = (w.x >> 16) & 0xff, j3 = (w.x >> 24) & 0xff;
            const int j4 =  w.y        & 0xff, j5 = (w.y >>  8) & 0xff;
            const int j6 = (w.y >> 16) & 0xff, j7 = (w.y >> 24) & 0xff;
            a0 = fmax4(a0, xs4[j0 * 32 + fl]);
            b0 = fmax4(b0, xs4[j0 * 32 + fl + 16]);
            a1 = fmax4(a1, xs4[j1 * 32 + fl]);
            b1 = fmax4(b1, xs4[j1 * 32 + fl + 16]);
            a0 = fmax4(a0, xs4[j2 * 32 + fl]);
            b0 = fmax4(b0, xs4[j2 * 32 + fl + 16]);
            a1 = fmax4(a1, xs4[j3 * 32 + fl]);
            b1 = fmax4(b1, xs4[j3 * 32 + fl + 16]);
            a0 = fmax4(a0, xs4[j4 * 32 + fl]);
            b0 = fmax4(b0, xs4[j4 * 32 + fl + 16]);
            a1 = fmax4(a1, xs4[j5 * 32 + fl]);
            b1 = fmax4(b1, xs4[j5 * 32 + fl + 16]);
            a0 = fmax4(a0, xs4[j6 * 32 + fl]);
            b0 = fmax4(b0, xs4[j6 * 32 + fl + 16]);
            a1 = fmax4(a1, xs4[j7 * 32 + fl]);
            b1 = fmax4(b1, xs4[j7 * 32 + fl + 16]);
        }
        resA = fmax4(a0, a1);
        resB = fmax4(b0, b1);
    }
    out4[(size_t)i * 32 + fl]      = resA;
    out4[(size_t)i * 32 + fl + 16] = resB;
}

extern "C" void kernel_launch(void* const* d_in, const int* in_sizes, int n_in,
                              void* d_out, int out_size)
{
    const float* node_features = (const float*)d_in[0];
    const float* laplacian     = (const float*)d_in[1];
    const int*   mol_slice     = (const int*)d_in[2];
    // d_in[3] = l_slice (unused)

    float* out = (float*)d_out;

    const int smem = AT * NF * sizeof(float);     // 64 KB dynamic
    cudaFuncSetAttribute(graph_pool_mol_kernel,
                         cudaFuncAttributeMaxDynamicSharedMemorySize, smem);

    const int B = 64;
    graph_pool_mol_kernel<<<B * ROW_GROUPS, THREADS, smem>>>(
        node_features, laplacian, mol_slice, out);
}

// round 4
// speedup vs baseline: 1.4388x; 1.0030x over previous
#include <cuda_runtime.h>
#include <math_constants.h>

// GraphPoolMol: masked neighborhood max-pool over graph Laplacian sparsity.
// B=64, MAX_ATOM=128, N_FEAT=128.
// out[b,i,f] = max_{j: L[b,i,j]!=0, j<n, i<n} x[b,j,f]; 0 if i>=n.
// diag(L)=1 => every valid row contains self => cnt==0 <=> i>=n, and padding
// the neighbor list with the self index never changes the max.

#define AT 128
#define NF 128
#define ROW_GROUPS 4
#define RPB 32                 // rows per block
#define THREADS 512
#define ITS 8                  // RPB*AT / THREADS
#define X_BYTES (AT * NF * 4)  // 64 KB

__device__ __forceinline__ float4 fmax4(float4 a, float4 b) {
    return make_float4(fmaxf(a.x, b.x), fmaxf(a.y, b.y),
                       fmaxf(a.z, b.z), fmaxf(a.w, b.w));
}

__global__ __launch_bounds__(THREADS, 2)
void graph_pool_mol_kernel(const float* __restrict__ xg,
                           const float* __restrict__ Lg,
                           const int* __restrict__ mol_slice,
                           float* __restrict__ outg)
{
    const int b  = blockIdx.x >> 2;
    const int rg = blockIdx.x & 3;

    extern __shared__ float xs[];                 // AT*NF floats = 64 KB
    __shared__ unsigned      words[RPB][4];       // 128-bit nonzero masks
    __shared__ unsigned char list[RPB][AT];       // compacted neighbor indices
    __shared__ int           cnts[RPB];
    __shared__ __align__(8) unsigned long long mbar;

    const int n   = mol_slice[2 * b];             // mol_slice[b,0] = n_atoms
    const int tid = threadIdx.x;

    // ---- Stage x[b] -> shared via ONE bulk TMA copy (zero SM issue cost) --
    const unsigned mbar_s = (unsigned)__cvta_generic_to_shared(&mbar);
    if (tid == 0) {
        asm volatile("mbarrier.init.shared.b64 [%0], %1;"
                     :: "r"(mbar_s), "r"(1) : "memory");
        asm volatile("mbarrier.arrive.expect_tx.shared.b64 _, [%0], %1;"
                     :: "r"(mbar_s), "r"(X_BYTES) : "memory");
        const unsigned xs_s = (unsigned)__cvta_generic_to_shared(xs);
        asm volatile(
            "cp.async.bulk.shared::cta.global.mbarrier::complete_tx::bytes "
            "[%0], [%1], %2, [%3];"
            :: "r"(xs_s), "l"(xg + (size_t)b * AT * NF), "r"(X_BYTES),
               "r"(mbar_s) : "memory");
    }

    const int f    = tid & (AT - 1);   // j index within row, 0..127
    const int ry   = tid >> 7;         // row slot, 0..3
    const int wrow = f >> 5;           // ballot word index, 0..3
    const int lane = f & 31;
    const int base = rg * RPB;

    const float* Lb = Lg + (size_t)b * AT * AT;

    // ---- Preload all L values (MLP=8, single memory epoch) ---------------
    float Lv[ITS];
    #pragma unroll
    for (int it = 0; it < ITS; ++it) {
        const int i = base + it * 4 + ry;
        Lv[it] = Lb[(size_t)i * AT + f];
    }

    // ---- All ballots, no barriers -----------------------------------------
    unsigned nbmask = 0;
    #pragma unroll
    for (int it = 0; it < ITS; ++it) {
        const int r = it * 4 + ry;
        const int i = base + r;
        const bool nb = (Lv[it] != 0.0f) && (f < n) && (i < n);
        nbmask |= nb ? (1u << it) : 0u;
        const unsigned bal = __ballot_sync(0xffffffffu, nb);
        if (lane == 0) words[r][wrow] = bal;
    }
    __syncthreads();   // words visible (also orders mbarrier.init vs waits)

    // ---- Build compacted neighbor lists (pure LDS, no barriers) -----------
    #pragma unroll
    for (int it = 0; it < ITS; ++it) {
        const int r = it * 4 + ry;
        const int i = base + r;
        const uint4 w = *reinterpret_cast<const uint4*>(words[r]);
        const int c0 = __popc(w.x), c1 = __popc(w.y), c2 = __popc(w.z);
        const int cnt = c0 + c1 + c2 + __popc(w.w);
        if (f == 0) cnts[r] = cnt;

        if (nbmask & (1u << it)) {
            const unsigned myw = (wrow == 0) ? w.x : (wrow == 1) ? w.y
                               : (wrow == 2) ? w.z : w.w;
            const int pre = (wrow > 0 ? c0 : 0) + (wrow > 1 ? c1 : 0)
                          + (wrow > 2 ? c2 : 0);
            const int pos = pre + __popc(myw & ((1u << lane) - 1u));
            list[r][pos] = (unsigned char)f;
        }
        // Pad to a multiple of 8 with the self index.
        const int cntpad = (cnt + 7) & ~7;
        if (f >= cnt && f < cntpad)
            list[r][f] = (unsigned char)i;
    }
    __syncthreads();   // lists visible

    // ---- Wait for the staged x tile (TMA completion) -----------------------
    {
        unsigned done;
        asm volatile(
            "{\n\t"
            ".reg .pred p;\n\t"
            "mbarrier.try_wait.parity.acquire.cta.shared::cta.b64 p, [%1], %2;\n\t"
            "selp.b32 %0, 1, 0, p;\n\t"
            "}"
            : "=r"(done) : "r"(mbar_s), "r"(0) : "memory");
        if (!done) {
            asm volatile(
                "{\n\t"
                ".reg .pred P1;\n\t"
                "W_%=:\n\t"
                "mbarrier.try_wait.parity.acquire.cta.shared::cta.b64 P1, [%0], %1, 0x989680;\n\t"
                "@P1 bra.uni D_%=;\n\t"
                "bra.uni W_%=;\n\t"
                "D_%=:\n\t"
                "}"
                :: "r"(mbar_s), "r"(0) : "memory");
        }
    }

    // ---- Gather: 32 rows in one pass, 16 threads/row, 8-neighbor unroll ---
    const int rb = tid >> 4;          // local row, 0..31
    const int fl = tid & 15;          // float4 slot, 0..15 (owns fl and fl+16)
    const int i  = base + rb;
    const int cnt = cnts[rb];
    const float4* xs4  = reinterpret_cast<const float4*>(xs);
    float4*       out4 = reinterpret_cast<float4*>(outg + (size_t)b * AT * NF);

    float4 resA, resB;
    if (cnt == 0) {                               // i >= n
        resA = make_float4(0.f, 0.f, 0.f, 0.f);
        resB = resA;
    } else {
        const float4 ninf = make_float4(-CUDART_INF_F, -CUDART_INF_F,
                                        -CUDART_INF_F, -CUDART_INF_F);
        float4 a0 = ninf, a1 = ninf, b0 = ninf, b1 = ninf;
        const unsigned char* lp = list[rb];
        const int cp = (cnt + 7) & ~7;
        for (int k = 0; k < cp; k += 8) {
            const uint2 w = *reinterpret_cast<const uint2*>(lp + k);  // 8 idx
            const int j0 =  w.x        & 0xff, j1 = (w.x >>  8) & 0xff;
            const int j2 = (w.x >> 16) & 0xff, j3 = (w.x >> 24) & 0xff;
            const int j4 =  w.y        & 0xff, j5 = (w.y >>  8) & 0xff;
            const int j6 = (w.y >> 16) & 0xff, j7 = (w.y >> 24) & 0xff;
            a0 = fmax4(a0, xs4[j0 * 32 + fl]);
            b0 = fmax4(b0, xs4[j0 * 32 + fl + 16]);
            a1 = fmax4(a1, xs4[j1 * 32 + fl]);
            b1 = fmax4(b1, xs4[j1 * 32 + fl + 16]);
            a0 = fmax4(a0, xs4[j2 * 32 + fl]);
            b0 = fmax4(b0, xs4[j2 * 32 + fl + 16]);
            a1 = fmax4(a1, xs4[j3 * 32 + fl]);
            b1 = fmax4(b1, xs4[j3 * 32 + fl + 16]);
            a0 = fmax4(a0, xs4[j4 * 32 + fl]);
            b0 = fmax4(b0, xs4[j4 * 32 + fl + 16]);
            a1 = fmax4(a1, xs4[j5 * 32 + fl]);
            b1 = fmax4(b1, xs4[j5 * 32 + fl + 16]);
            a0 = fmax4(a0, xs4[j6 * 32 + fl]);
            b0 = fmax4(b0, xs4[j6 * 32 + fl + 16]);
            a1 = fmax4(a1, xs4[j7 * 32 + fl]);
            b1 = fmax4(b1, xs4[j7 * 32 + fl + 16]);
        }
        resA = fmax4(a0, a1);
        resB = fmax4(b0, b1);
    }
    out4[(size_t)i * 32 + fl]      = resA;
    out4[(size_t)i * 32 + fl + 16] = resB;
}

extern "C" void kernel_launch(void* const* d_in, const int* in_sizes, int n_in,
                              void* d_out, int out_size)
{
    const float* node_features = (const float*)d_in[0];
    const float* laplacian     = (const float*)d_in[1];
    const int*   mol_slice     = (const int*)d_in[2];
    // d_in[3] = l_slice (unused)

    float* out = (float*)d_out;

    const int smem = X_BYTES;                     // 64 KB dynamic
    cudaFuncSetAttribute(graph_pool_mol_kernel,
                         cudaFuncAttributeMaxDynamicSharedMemorySize, smem);

    const int B = 64;
    graph_pool_mol_kernel<<<B * ROW_GROUPS, THREADS, smem>>>(
        node_features, laplacian, mol_slice, out);
}

// round 5
// speedup vs baseline: 1.7276x; 1.2007x over previous
#include <cuda_runtime.h>
#include <math_constants.h>

// GraphPoolMol: masked neighborhood max-pool over graph Laplacian sparsity.
// B=64, MAX_ATOM=128, N_FEAT=128.
// out[b,i,f] = max_{j: L[b,i,j]!=0, j<n, i<n} x[b,j,f]; 0 if i>=n.
// diag(L)=1 => every valid row (i<n) contains j=i, so "no neighbor" fallback
// never fires for valid rows: mask==0 <=> i>=n.
//
// One warp owns one row end-to-end: lane l handles features 4l..4l+3.
// The row's 128-bit nonzero mask lives in 4 ballot words in registers.
// No cross-warp smem, no list compaction, one __syncthreads total.

#define AT 128
#define NF 128
#define ROW_GROUPS 8
#define RPB 16                  // rows per block = warps per block
#define THREADS 512
#define X_BYTES (AT * NF * 4)   // 64 KB

__device__ __forceinline__ float4 fmax4(float4 a, float4 b) {
    return make_float4(fmaxf(a.x, b.x), fmaxf(a.y, b.y),
                       fmaxf(a.z, b.z), fmaxf(a.w, b.w));
}

__global__ __launch_bounds__(THREADS, 3)
void graph_pool_mol_kernel(const float* __restrict__ xg,
                           const float* __restrict__ Lg,
                           const int* __restrict__ mol_slice,
                           float* __restrict__ outg)
{
    const int b  = blockIdx.x >> 3;
    const int rg = blockIdx.x & 7;

    extern __shared__ float xs[];                 // 64 KB x tile
    __shared__ __align__(8) unsigned long long mbar;

    const int tid  = threadIdx.x;
    const int wid  = tid >> 5;
    const int lane = tid & 31;

    const unsigned mbar_s = (unsigned)__cvta_generic_to_shared(&mbar);
    if (tid == 0) {
        asm volatile("mbarrier.init.shared.b64 [%0], %1;"
                     :: "r"(mbar_s), "r"(1) : "memory");
    }
    __syncthreads();                              // init visible to all warps
    if (tid == 0) {
        asm volatile("mbarrier.arrive.expect_tx.shared.b64 _, [%0], %1;"
                     :: "r"(mbar_s), "r"(X_BYTES) : "memory");
        const unsigned xs_s = (unsigned)__cvta_generic_to_shared(xs);
        asm volatile(
            "cp.async.bulk.shared::cta.global.mbarrier::complete_tx::bytes "
            "[%0], [%1], %2, [%3];"
            :: "r"(xs_s), "l"(xg + (size_t)b * AT * NF), "r"(X_BYTES),
               "r"(mbar_s) : "memory");
    }

    // ---- Per-warp: load L row, build mask in registers (overlaps TMA) -----
    const int n = __ldg(mol_slice + 2 * b);       // mol_slice[b,0] = n_atoms
    const int i = rg * RPB + wid;                 // this warp's row

    const float4 Lv = __ldg(reinterpret_cast<const float4*>(
                                Lg + ((size_t)b * AT + i) * AT) + lane);

    const bool iv = (i < n);
    const int  j0 = 4 * lane;
    const unsigned w0 = __ballot_sync(0xffffffffu, iv && (Lv.x != 0.0f) && (j0 + 0 < n));
    const unsigned w1 = __ballot_sync(0xffffffffu, iv && (Lv.y != 0.0f) && (j0 + 1 < n));
    const unsigned w2 = __ballot_sync(0xffffffffu, iv && (Lv.z != 0.0f) && (j0 + 2 < n));
    const unsigned w3 = __ballot_sync(0xffffffffu, iv && (Lv.w != 0.0f) && (j0 + 3 < n));
    const bool any = (w0 | w1 | w2 | w3) != 0u;   // <=> i < n

    // ---- Wait for the staged x tile ----------------------------------------
    {
        unsigned done;
        asm volatile(
            "{\n\t"
            ".reg .pred p;\n\t"
            "mbarrier.try_wait.parity.acquire.cta.shared::cta.b64 p, [%1], %2;\n\t"
            "selp.b32 %0, 1, 0, p;\n\t"
            "}"
            : "=r"(done) : "r"(mbar_s), "r"(0) : "memory");
        if (!done) {
            asm volatile(
                "{\n\t"
                ".reg .pred P1;\n\t"
                "W_%=:\n\t"
                "mbarrier.try_wait.parity.acquire.cta.shared::cta.b64 P1, [%0], %1, 0x989680;\n\t"
                "@P1 bra.uni D_%=;\n\t"
                "bra.uni W_%=;\n\t"
                "D_%=:\n\t"
                "}"
                :: "r"(mbar_s), "r"(0) : "memory");
        }
    }

    // ---- Gather: iterate mask bits; lane l reads feats 4l..4l+3 of atom j --
    const float4* xs4 = reinterpret_cast<const float4*>(xs);
    float4 res;
    if (!any) {
        res = make_float4(0.f, 0.f, 0.f, 0.f);
    } else {
        float4 a0 = make_float4(-CUDART_INF_F, -CUDART_INF_F,
                                -CUDART_INF_F, -CUDART_INF_F);
        float4 a1 = a0;
        // Word q contributes columns j = 4*bit + q.
        unsigned m0 = w0, m1 = w1, m2 = w2, m3 = w3;
        while (m0) { const int t = __ffs(m0) - 1; m0 &= m0 - 1;
                     a0 = fmax4(a0, xs4[(4 * t + 0) * 32 + lane]); }
        while (m1) { const int t = __ffs(m1) - 1; m1 &= m1 - 1;
                     a1 = fmax4(a1, xs4[(4 * t + 1) * 32 + lane]); }
        while (m2) { const int t = __ffs(m2) - 1; m2 &= m2 - 1;
                     a0 = fmax4(a0, xs4[(4 * t + 2) * 32 + lane]); }
        while (m3) { const int t = __ffs(m3) - 1; m3 &= m3 - 1;
                     a1 = fmax4(a1, xs4[(4 * t + 3) * 32 + lane]); }
        res = fmax4(a0, a1);
    }

    float4* out4 = reinterpret_cast<float4*>(outg);
    out4[((size_t)b * AT + i) * 32 + lane] = res;
}

extern "C" void kernel_launch(void* const* d_in, const int* in_sizes, int n_in,
                              void* d_out, int out_size)
{
    const float* node_features = (const float*)d_in[0];
    const float* laplacian     = (const float*)d_in[1];
    const int*   mol_slice     = (const int*)d_in[2];
    // d_in[3] = l_slice (unused)

    float* out = (float*)d_out;

    cudaFuncSetAttribute(graph_pool_mol_kernel,
                         cudaFuncAttributeMaxDynamicSharedMemorySize, X_BYTES);

    const int B = 64;
    graph_pool_mol_kernel<<<B * ROW_GROUPS, THREADS, X_BYTES>>>(
        node_features, laplacian, mol_slice, out);
}